// round 4
// baseline (speedup 1.0000x reference)
#include <cuda_runtime.h>
#include <math.h>

#define TGTN 2048
#define SRCN 4096
#define DIMN 512
#define NHEAD 8
#define HDIM 64
#define NVOC 32000
#define EXTV 36096

// ---------------- scratch (device globals; no allocation allowed) ----------
__device__ float g_Q[TGTN * DIMN];                         // 4 MB
__device__ float g_K[SRCN * DIMN];                         // 8 MB
__device__ float g_S[(size_t)NHEAD * TGTN * SRCN];         // 256 MB raw scores
__device__ float g_attn[(size_t)TGTN * SRCN];              // 32 MB head-mean attn
__device__ float g_lk[TGTN];                               // log_keep
__device__ float g_lc[TGTN];                               // log_copy

// ---------------- helpers ---------------------------------------------------
__device__ __forceinline__ float log_sigmoid_f(float x) {
    return fminf(x, 0.0f) - log1pf(expf(-fabsf(x)));
}
__device__ __forceinline__ float warp_max(float v) {
    #pragma unroll
    for (int o = 16; o > 0; o >>= 1) v = fmaxf(v, __shfl_xor_sync(0xffffffffu, v, o));
    return v;
}
__device__ __forceinline__ float warp_sum(float v) {
    #pragma unroll
    for (int o = 16; o > 0; o >>= 1) v += __shfl_xor_sync(0xffffffffu, v, o);
    return v;
}

// ---------------- kernel 1: z / log_copy / log_keep -------------------------
// one warp per target row
__global__ void __launch_bounds__(256) z_kernel(
    const float* __restrict__ tgt, const float* __restrict__ w_lin,
    const float* __restrict__ b_lin)
{
    int row  = blockIdx.x * 8 + (threadIdx.x >> 5);
    int lane = threadIdx.x & 31;
    if (row >= TGTN) return;
    const float* tp = tgt + (size_t)row * DIMN;
    float s = 0.0f;
    #pragma unroll
    for (int i = 0; i < DIMN / 32; i++) s += tp[lane + i * 32] * w_lin[lane + i * 32];
    s = warp_sum(s);
    if (lane == 0) {
        float z = s + b_lin[0];
        g_lc[row] = log_sigmoid_f(z);    // log(copy)
        g_lk[row] = log_sigmoid_f(-z);   // log(1-copy)
    }
}

// ---------------- kernel 2: projection GEMM  C[M,512] = A[M,512] @ W[512,512]
// 128x64 block tile, 256 threads, 8x4 per-thread microtile, k-chunks of 32.
__global__ void __launch_bounds__(256) proj_gemm(
    const float* __restrict__ A, const float* __restrict__ W,
    float* __restrict__ C)
{
    __shared__ float As[32 * 132];   // [kk][r], r<128, pitch 132 (16B-aligned rows)
    __shared__ float Ws[32 * 68];    // [kk][c], c<64,  pitch 68

    const int tx = threadIdx.x & 15;
    const int ty = threadIdx.x >> 4;
    const int r0 = blockIdx.y * 128;
    const int c0 = blockIdx.x * 64;

    float acc[8][4];
    #pragma unroll
    for (int i = 0; i < 8; i++)
        #pragma unroll
        for (int j = 0; j < 4; j++) acc[i][j] = 0.0f;

    for (int k0 = 0; k0 < DIMN; k0 += 32) {
        __syncthreads();
        #pragma unroll
        for (int t = 0; t < 16; t++) {                 // 128*32 / 256
            int i  = threadIdx.x + t * 256;
            int r  = i >> 5, kk = i & 31;
            As[kk * 132 + r] = A[(size_t)(r0 + r) * DIMN + k0 + kk];
        }
        #pragma unroll
        for (int t = 0; t < 8; t++) {                  // 64*32 / 256
            int i  = threadIdx.x + t * 256;
            int kk = i >> 6, c = i & 63;
            Ws[kk * 68 + c] = W[(size_t)(k0 + kk) * DIMN + c0 + c];
        }
        __syncthreads();
        #pragma unroll
        for (int kk = 0; kk < 32; kk++) {
            float4 a0 = *(const float4*)&As[kk * 132 + ty * 4];
            float4 a1 = *(const float4*)&As[kk * 132 + 64 + ty * 4];
            float4 b  = *(const float4*)&Ws[kk * 68 + tx * 4];
            float av[8] = {a0.x, a0.y, a0.z, a0.w, a1.x, a1.y, a1.z, a1.w};
            float bv[4] = {b.x, b.y, b.z, b.w};
            #pragma unroll
            for (int i = 0; i < 8; i++)
                #pragma unroll
                for (int j = 0; j < 4; j++)
                    acc[i][j] = fmaf(av[i], bv[j], acc[i][j]);
        }
    }
    #pragma unroll
    for (int i = 0; i < 8; i++) {
        int row = r0 + ((i < 4) ? (ty * 4 + i) : (64 + ty * 4 + (i - 4)));
        float4 v = make_float4(acc[i][0], acc[i][1], acc[i][2], acc[i][3]);
        *(float4*)&C[(size_t)row * DIMN + c0 + tx * 4] = v;
    }
}

// ---------------- kernel 3: per-head scores  S[h,t,s] = 0.125 * Qh[t,:]·Kh[s,:]
// 128x128 tile, 256 threads, 8x8 microtile, K=64 in two 32-chunks.
__global__ void __launch_bounds__(256) scores_gemm()
{
    __shared__ float Qs[32 * 132];   // [kk][t]
    __shared__ float Ks[32 * 132];   // [kk][s]

    const int tx = threadIdx.x & 15;
    const int ty = threadIdx.x >> 4;
    const int s0 = blockIdx.x * 128;
    const int t0 = blockIdx.y * 128;
    const int h  = blockIdx.z;

    float acc[8][8];
    #pragma unroll
    for (int i = 0; i < 8; i++)
        #pragma unroll
        for (int j = 0; j < 8; j++) acc[i][j] = 0.0f;

    for (int k0 = 0; k0 < HDIM; k0 += 32) {
        __syncthreads();
        #pragma unroll
        for (int t = 0; t < 16; t++) {
            int i  = threadIdx.x + t * 256;
            int r  = i >> 5, kk = i & 31;
            Qs[kk * 132 + r] = g_Q[(size_t)(t0 + r) * DIMN + h * HDIM + k0 + kk];
            Ks[kk * 132 + r] = g_K[(size_t)(s0 + r) * DIMN + h * HDIM + k0 + kk];
        }
        __syncthreads();
        #pragma unroll
        for (int kk = 0; kk < 32; kk++) {
            float4 a0 = *(const float4*)&Qs[kk * 132 + ty * 4];
            float4 a1 = *(const float4*)&Qs[kk * 132 + 64 + ty * 4];
            float4 b0 = *(const float4*)&Ks[kk * 132 + tx * 4];
            float4 b1 = *(const float4*)&Ks[kk * 132 + 64 + tx * 4];
            float av[8] = {a0.x, a0.y, a0.z, a0.w, a1.x, a1.y, a1.z, a1.w};
            float bv[8] = {b0.x, b0.y, b0.z, b0.w, b1.x, b1.y, b1.z, b1.w};
            #pragma unroll
            for (int i = 0; i < 8; i++)
                #pragma unroll
                for (int j = 0; j < 8; j++)
                    acc[i][j] = fmaf(av[i], bv[j], acc[i][j]);
        }
    }
    #pragma unroll
    for (int i = 0; i < 8; i++) {
        int trow = t0 + ((i < 4) ? (ty * 4 + i) : (64 + ty * 4 + (i - 4)));
        float* op = &g_S[((size_t)h * TGTN + trow) * SRCN + s0];
        float4 v0 = make_float4(acc[i][0] * 0.125f, acc[i][1] * 0.125f,
                                acc[i][2] * 0.125f, acc[i][3] * 0.125f);
        float4 v1 = make_float4(acc[i][4] * 0.125f, acc[i][5] * 0.125f,
                                acc[i][6] * 0.125f, acc[i][7] * 0.125f);
        *(float4*)(op + tx * 4)      = v0;
        *(float4*)(op + 64 + tx * 4) = v1;
    }
}

// ---------------- kernel 4: softmax per (h,t) over s, mean over heads -------
// one block per target row t; 256 threads; each thread owns 16 s-slots in regs.
__global__ void __launch_bounds__(256) softmax_mean()
{
    __shared__ float red[8];
    const int t    = blockIdx.x;
    const int tid  = threadIdx.x;
    const int lane = tid & 31;
    const int wid  = tid >> 5;

    float accr[16];
    #pragma unroll
    for (int j = 0; j < 16; j++) accr[j] = 0.0f;

    for (int h = 0; h < NHEAD; h++) {
        const float* sp = &g_S[((size_t)h * TGTN + t) * SRCN];
        float v[16];
        float m = -3.0e38f;
        #pragma unroll
        for (int j = 0; j < 16; j++) {
            v[j] = sp[tid + j * 256];
            m = fmaxf(m, v[j]);
        }
        m = warp_max(m);
        if (lane == 0) red[wid] = m;
        __syncthreads();
        float mx = red[0];
        #pragma unroll
        for (int w = 1; w < 8; w++) mx = fmaxf(mx, red[w]);
        __syncthreads();

        float s = 0.0f;
        #pragma unroll
        for (int j = 0; j < 16; j++) {
            v[j] = __expf(v[j] - mx);
            s += v[j];
        }
        s = warp_sum(s);
        if (lane == 0) red[wid] = s;
        __syncthreads();
        float tot = 0.0f;
        #pragma unroll
        for (int w = 0; w < 8; w++) tot += red[w];
        __syncthreads();

        float inv = 0.125f / tot;
        #pragma unroll
        for (int j = 0; j < 16; j++) accr[j] += v[j] * inv;
    }
    float* ap = &g_attn[(size_t)t * SRCN];
    #pragma unroll
    for (int j = 0; j < 16; j++) ap[tid + j * 256] = accr[j];
}

// ---------------- kernel 5: fused scatter + log_softmax + logaddexp ---------
// one block per target row; smem ext[36096] scatter table + reduction buffer.
// out[t,v] = log( exp(dec[t,v]+log_keep) + ext_attn[t,v] * copy_prob )
//   non-hit v<32000  -> dec+log_keep (exact)
//   non-hit v>=32000 -> -1e9 (exact)
__global__ void __launch_bounds__(1024) final_kernel(
    const float* __restrict__ logits, const int* __restrict__ ids,
    float* __restrict__ out)
{
    extern __shared__ float smem[];
    float* ext = smem;            // EXTV floats
    float* red = smem + EXTV;     // 32 floats

    const int t    = blockIdx.x;
    const int tid  = threadIdx.x;
    const int lane = tid & 31;
    const int wid  = tid >> 5;

    for (int i = tid; i < EXTV; i += 1024) ext[i] = 0.0f;
    __syncthreads();

    const float* ap = &g_attn[(size_t)t * SRCN];
    for (int s = tid; s < SRCN; s += 1024)
        atomicAdd(&ext[ids[s]], ap[s]);
    __syncthreads();

    const float* lg = logits + (size_t)t * NVOC;

    // row max
    float m = -3.0e38f;
    for (int i = tid; i < NVOC; i += 1024) m = fmaxf(m, lg[i]);
    m = warp_max(m);
    if (lane == 0) red[wid] = m;
    __syncthreads();
    if (wid == 0) {
        float x = red[lane];
        x = warp_max(x);
        if (lane == 0) red[0] = x;
    }
    __syncthreads();
    const float mx = red[0];
    __syncthreads();

    // row sum(exp)
    float s = 0.0f;
    for (int i = tid; i < NVOC; i += 1024) s += __expf(lg[i] - mx);
    s = warp_sum(s);
    if (lane == 0) red[wid] = s;
    __syncthreads();
    if (wid == 0) {
        float x = red[lane];
        x = warp_sum(x);
        if (lane == 0) red[0] = x;
    }
    __syncthreads();
    const float lse = mx + __logf(red[0]);

    const float lk    = g_lk[t];
    const float lc    = g_lc[t];
    const float copyp = __expf(lc);

    float* op = out + (size_t)t * EXTV;
    for (int v = tid; v < EXTV; v += 1024) {
        float base = (v < NVOC) ? (lg[v] - lse + lk) : -1e9f;
        float e = ext[v];
        float o;
        if (e > 0.0f) o = __logf(__expf(base) + e * copyp);
        else          o = base;
        op[v] = o;
    }
}

// ---------------- host launcher ---------------------------------------------
extern "C" void kernel_launch(void* const* d_in, const int* in_sizes, int n_in,
                              void* d_out, int out_size)
{
    const float* logits = (const float*)d_in[0];
    const int*   ids    = (const int*)d_in[1];
    const float* src    = (const float*)d_in[2];
    const float* tgt    = (const float*)d_in[3];
    const float* w_lin;
    const float* b_lin;
    const float* Wq;
    const float* Wk;
    // len_extended_vocab (scalar) may or may not occupy slot 4
    if (n_in >= 9 && in_sizes[4] == 1) {
        w_lin = (const float*)d_in[5];
        b_lin = (const float*)d_in[6];
        Wq    = (const float*)d_in[7];
        Wk    = (const float*)d_in[8];
    } else {
        w_lin = (const float*)d_in[4];
        b_lin = (const float*)d_in[5];
        Wq    = (const float*)d_in[6];
        Wk    = (const float*)d_in[7];
    }

    static bool   inited = false;
    static float* pQ = nullptr;
    static float* pK = nullptr;
    if (!inited) {
        cudaFuncSetAttribute(final_kernel,
                             cudaFuncAttributeMaxDynamicSharedMemorySize,
                             (EXTV + 32) * (int)sizeof(float));
        void* tmp;
        cudaGetSymbolAddress(&tmp, g_Q); pQ = (float*)tmp;
        cudaGetSymbolAddress(&tmp, g_K); pK = (float*)tmp;
        inited = true;
    }

    float* out = (float*)d_out;

    // 1) gating scalars
    z_kernel<<<TGTN / 8, 256>>>(tgt, w_lin, b_lin);

    // 2) projections
    proj_gemm<<<dim3(DIMN / 64, TGTN / 128), 256>>>(tgt, Wq, pQ);
    proj_gemm<<<dim3(DIMN / 64, SRCN / 128), 256>>>(src, Wk, pK);

    // 3) per-head raw scores
    scores_gemm<<<dim3(SRCN / 128, TGTN / 128, NHEAD), 256>>>();

    // 4) softmax + head mean
    softmax_mean<<<TGTN, 256>>>();

    // 5) fused scatter + log_softmax + combine
    final_kernel<<<TGTN, 1024, (EXTV + 32) * (int)sizeof(float)>>>(logits, ids, out);
}

// round 5
// speedup vs baseline: 1.8590x; 1.8590x over previous
#include <cuda_runtime.h>
#include <cuda_bf16.h>
#include <math.h>

#define TGTN 2048
#define SRCN 4096
#define DIMN 512
#define NHEAD 8
#define HDIM 64
#define NVOC 32000
#define EXTV 36096

// ---------------- scratch (device globals; no allocation allowed) ----------
__device__ float         g_Q[TGTN * DIMN];                       // 4 MB
__device__ float         g_K[SRCN * DIMN];                       // 8 MB
__device__ __nv_bfloat16 g_Sb[(size_t)NHEAD * TGTN * SRCN];      // 128 MB scores (bf16)
__device__ float         g_attn[(size_t)TGTN * SRCN];            // 32 MB head-mean attn
__device__ float         g_lk[TGTN];                             // log_keep
__device__ float         g_lc[TGTN];                             // log_copy

// ---------------- helpers ---------------------------------------------------
__device__ __forceinline__ float log_sigmoid_f(float x) {
    return fminf(x, 0.0f) - log1pf(expf(-fabsf(x)));
}
__device__ __forceinline__ float warp_max(float v) {
    #pragma unroll
    for (int o = 16; o > 0; o >>= 1) v = fmaxf(v, __shfl_xor_sync(0xffffffffu, v, o));
    return v;
}
__device__ __forceinline__ float warp_sum(float v) {
    #pragma unroll
    for (int o = 16; o > 0; o >>= 1) v += __shfl_xor_sync(0xffffffffu, v, o);
    return v;
}
__device__ __forceinline__ float f2tf32(float x) {
    unsigned u;
    asm("cvt.rna.tf32.f32 %0, %1;" : "=r"(u) : "f"(x));
    return __uint_as_float(u);
}
__device__ __forceinline__ float4 tf32x4(float4 v) {
    v.x = f2tf32(v.x); v.y = f2tf32(v.y); v.z = f2tf32(v.z); v.w = f2tf32(v.w);
    return v;
}
// D += A(16x8,row) * B(8x8,col), tf32 inputs, f32 accumulate
__device__ __forceinline__ void mma_tf32(float* c, const unsigned* a, const unsigned* b) {
    asm volatile(
        "mma.sync.aligned.m16n8k8.row.col.f32.tf32.tf32.f32 "
        "{%0,%1,%2,%3},{%4,%5,%6,%7},{%8,%9},{%0,%1,%2,%3};\n"
        : "+f"(c[0]), "+f"(c[1]), "+f"(c[2]), "+f"(c[3])
        : "r"(a[0]), "r"(a[1]), "r"(a[2]), "r"(a[3]), "r"(b[0]), "r"(b[1]));
}

// ---------------- kernel 1: z / log_copy / log_keep -------------------------
__global__ void __launch_bounds__(256) z_kernel(
    const float* __restrict__ tgt, const float* __restrict__ w_lin,
    const float* __restrict__ b_lin)
{
    int row  = blockIdx.x * 8 + (threadIdx.x >> 5);
    int lane = threadIdx.x & 31;
    if (row >= TGTN) return;
    const float* tp = tgt + (size_t)row * DIMN;
    float s = 0.0f;
    #pragma unroll
    for (int i = 0; i < DIMN / 32; i++) s += tp[lane + i * 32] * w_lin[lane + i * 32];
    s = warp_sum(s);
    if (lane == 0) {
        float z = s + b_lin[0];
        g_lc[row] = log_sigmoid_f(z);    // log(copy)
        g_lk[row] = log_sigmoid_f(-z);   // log(1-copy)
    }
}

// ---------------- kernel 2: projection GEMM (tf32 mma) ----------------------
// C[M,512] = A[M,512] @ W[512,512].  128x128 block tile, 8 warps (2x4),
// 64x32 warp tile, k-chunk 32, fragments loaded from smem by formula.
__global__ void __launch_bounds__(256, 2) proj_gemm_t(
    const float* __restrict__ A, const float* __restrict__ W,
    float* __restrict__ C)
{
    __shared__ float As[128 * 36];   // [m][k], pitch 36 (== 4 mod 32)
    __shared__ float Ws[32 * 136];   // [k][n], pitch 136 (== 8 mod 32)

    const int tid    = threadIdx.x;
    const int lane   = tid & 31;
    const int wid    = tid >> 5;
    const int warp_m = wid & 1;       // 0..1
    const int warp_n = wid >> 1;      // 0..3
    const int g      = lane >> 2;     // groupID 0..7
    const int tg     = lane & 3;      // thread in group 0..3
    const int r0     = blockIdx.y * 128;
    const int c0     = blockIdx.x * 128;

    float acc[4][4][4];
    #pragma unroll
    for (int i = 0; i < 4; i++)
        #pragma unroll
        for (int j = 0; j < 4; j++)
            #pragma unroll
            for (int q = 0; q < 4; q++) acc[i][j][q] = 0.0f;

    for (int kc = 0; kc < DIMN; kc += 32) {
        __syncthreads();
        #pragma unroll
        for (int t = 0; t < 4; t++) {                  // A: 128x32 = 1024 float4
            int idx = tid + t * 256;
            int r = idx >> 3, c4 = idx & 7;
            float4 v = *(const float4*)&A[(size_t)(r0 + r) * DIMN + kc + c4 * 4];
            *(float4*)&As[r * 36 + c4 * 4] = tf32x4(v);
        }
        #pragma unroll
        for (int t = 0; t < 4; t++) {                  // W: 32x128 = 1024 float4
            int idx = tid + t * 256;
            int kr = idx >> 5, c4 = idx & 31;
            float4 v = *(const float4*)&W[(size_t)(kc + kr) * DIMN + c0 + c4 * 4];
            *(float4*)&Ws[kr * 136 + c4 * 4] = tf32x4(v);
        }
        __syncthreads();

        #pragma unroll
        for (int k0 = 0; k0 < 32; k0 += 8) {
            unsigned a[4][4], b[4][2];
            #pragma unroll
            for (int mi = 0; mi < 4; mi++) {
                int mb = warp_m * 64 + mi * 16;
                a[mi][0] = __float_as_uint(As[(mb + g    ) * 36 + k0 + tg    ]);
                a[mi][1] = __float_as_uint(As[(mb + g + 8) * 36 + k0 + tg    ]);
                a[mi][2] = __float_as_uint(As[(mb + g    ) * 36 + k0 + tg + 4]);
                a[mi][3] = __float_as_uint(As[(mb + g + 8) * 36 + k0 + tg + 4]);
            }
            #pragma unroll
            for (int ni = 0; ni < 4; ni++) {
                int nb = warp_n * 32 + ni * 8;
                b[ni][0] = __float_as_uint(Ws[(k0 + tg    ) * 136 + nb + g]);
                b[ni][1] = __float_as_uint(Ws[(k0 + tg + 4) * 136 + nb + g]);
            }
            #pragma unroll
            for (int mi = 0; mi < 4; mi++)
                #pragma unroll
                for (int ni = 0; ni < 4; ni++)
                    mma_tf32(acc[mi][ni], a[mi], b[ni]);
        }
    }

    #pragma unroll
    for (int mi = 0; mi < 4; mi++) {
        int r = r0 + warp_m * 64 + mi * 16 + g;
        #pragma unroll
        for (int ni = 0; ni < 4; ni++) {
            int c = c0 + warp_n * 32 + ni * 8 + tg * 2;
            *(float2*)&C[(size_t)r * DIMN + c]       = make_float2(acc[mi][ni][0], acc[mi][ni][1]);
            *(float2*)&C[(size_t)(r + 8) * DIMN + c] = make_float2(acc[mi][ni][2], acc[mi][ni][3]);
        }
    }
}

// ---------------- kernel 3: per-head scores (tf32 mma, bf16 output) ---------
// S[h,t,s] = 0.125 * Qh[t,:]·Kh[s,:].  128x128 tile per block, K=64 in 2 chunks.
__global__ void __launch_bounds__(256, 2) scores_gemm_t()
{
    __shared__ float Qs[128 * 36];   // [t][k], pitch 36
    __shared__ float Ks[128 * 36];   // [s][k], pitch 36

    const int tid    = threadIdx.x;
    const int lane   = tid & 31;
    const int wid    = tid >> 5;
    const int warp_m = wid & 1;
    const int warp_n = wid >> 1;
    const int g      = lane >> 2;
    const int tg     = lane & 3;
    const int s0     = blockIdx.x * 128;
    const int t0     = blockIdx.y * 128;
    const int h      = blockIdx.z;

    float acc[4][4][4];
    #pragma unroll
    for (int i = 0; i < 4; i++)
        #pragma unroll
        for (int j = 0; j < 4; j++)
            #pragma unroll
            for (int q = 0; q < 4; q++) acc[i][j][q] = 0.0f;

    for (int kc = 0; kc < HDIM; kc += 32) {
        __syncthreads();
        #pragma unroll
        for (int t = 0; t < 4; t++) {                  // 128x32 floats each
            int idx = tid + t * 256;
            int r = idx >> 3, c4 = idx & 7;
            float4 q = *(const float4*)&g_Q[(size_t)(t0 + r) * DIMN + h * HDIM + kc + c4 * 4];
            *(float4*)&Qs[r * 36 + c4 * 4] = tf32x4(q);
            float4 k = *(const float4*)&g_K[(size_t)(s0 + r) * DIMN + h * HDIM + kc + c4 * 4];
            *(float4*)&Ks[r * 36 + c4 * 4] = tf32x4(k);
        }
        __syncthreads();

        #pragma unroll
        for (int k0 = 0; k0 < 32; k0 += 8) {
            unsigned a[4][4], b[4][2];
            #pragma unroll
            for (int mi = 0; mi < 4; mi++) {
                int mb = warp_m * 64 + mi * 16;
                a[mi][0] = __float_as_uint(Qs[(mb + g    ) * 36 + k0 + tg    ]);
                a[mi][1] = __float_as_uint(Qs[(mb + g + 8) * 36 + k0 + tg    ]);
                a[mi][2] = __float_as_uint(Qs[(mb + g    ) * 36 + k0 + tg + 4]);
                a[mi][3] = __float_as_uint(Qs[(mb + g + 8) * 36 + k0 + tg + 4]);
            }
            #pragma unroll
            for (int ni = 0; ni < 4; ni++) {
                int nb = warp_n * 32 + ni * 8;
                b[ni][0] = __float_as_uint(Ks[(nb + g) * 36 + k0 + tg    ]);
                b[ni][1] = __float_as_uint(Ks[(nb + g) * 36 + k0 + tg + 4]);
            }
            #pragma unroll
            for (int mi = 0; mi < 4; mi++)
                #pragma unroll
                for (int ni = 0; ni < 4; ni++)
                    mma_tf32(acc[mi][ni], a[mi], b[ni]);
        }
    }

    const size_t hb = (size_t)h * TGTN;
    #pragma unroll
    for (int mi = 0; mi < 4; mi++) {
        int r = t0 + warp_m * 64 + mi * 16 + g;
        #pragma unroll
        for (int ni = 0; ni < 4; ni++) {
            int c = s0 + warp_n * 32 + ni * 8 + tg * 2;
            *(__nv_bfloat162*)&g_Sb[(hb + r) * SRCN + c] =
                __floats2bfloat162_rn(acc[mi][ni][0] * 0.125f, acc[mi][ni][1] * 0.125f);
            *(__nv_bfloat162*)&g_Sb[(hb + r + 8) * SRCN + c] =
                __floats2bfloat162_rn(acc[mi][ni][2] * 0.125f, acc[mi][ni][3] * 0.125f);
        }
    }
}

// ---------------- kernel 4: softmax per (h,t) over s, mean over heads -------
__global__ void __launch_bounds__(256) softmax_mean()
{
    __shared__ float red[8];
    const int t    = blockIdx.x;
    const int tid  = threadIdx.x;
    const int lane = tid & 31;
    const int wid  = tid >> 5;

    float accr[16];
    #pragma unroll
    for (int j = 0; j < 16; j++) accr[j] = 0.0f;

    for (int h = 0; h < NHEAD; h++) {
        const __nv_bfloat162* sp =
            (const __nv_bfloat162*)(g_Sb + ((size_t)h * TGTN + t) * SRCN);
        float v[16];
        float m = -3.0e38f;
        #pragma unroll
        for (int j = 0; j < 8; j++) {
            float2 w = __bfloat1622float2(sp[tid + j * 256]);
            v[2 * j] = w.x; v[2 * j + 1] = w.y;
            m = fmaxf(m, fmaxf(w.x, w.y));
        }
        m = warp_max(m);
        if (lane == 0) red[wid] = m;
        __syncthreads();
        float mx = red[0];
        #pragma unroll
        for (int w = 1; w < 8; w++) mx = fmaxf(mx, red[w]);
        __syncthreads();

        float s = 0.0f;
        #pragma unroll
        for (int j = 0; j < 16; j++) {
            v[j] = __expf(v[j] - mx);
            s += v[j];
        }
        s = warp_sum(s);
        if (lane == 0) red[wid] = s;
        __syncthreads();
        float tot = 0.0f;
        #pragma unroll
        for (int w = 0; w < 8; w++) tot += red[w];
        __syncthreads();

        float inv = 0.125f / tot;
        #pragma unroll
        for (int j = 0; j < 16; j++) accr[j] += v[j] * inv;
    }
    float2* ap2 = (float2*)(g_attn + (size_t)t * SRCN);
    #pragma unroll
    for (int j = 0; j < 8; j++)
        ap2[tid + j * 256] = make_float2(accr[2 * j], accr[2 * j + 1]);
}

// ---------------- kernel 5: fused scatter + log_softmax + logaddexp ---------
// logits row cached in registers (1 HBM pass); no max pass (logits bounded).
__global__ void __launch_bounds__(1024) final_kernel(
    const float* __restrict__ logits, const int* __restrict__ ids,
    float* __restrict__ out)
{
    extern __shared__ float smem[];
    float* ext = smem;            // EXTV floats
    float* red = smem + EXTV;     // 32 floats

    const int t    = blockIdx.x;
    const int tid  = threadIdx.x;
    const int lane = tid & 31;
    const int wid  = tid >> 5;

    for (int i = tid; i < EXTV; i += 1024) ext[i] = 0.0f;
    __syncthreads();

    // scatter attn into extended-vocab table
    const float* ap = &g_attn[(size_t)t * SRCN];
    #pragma unroll
    for (int s = tid; s < SRCN; s += 1024)
        atomicAdd(&ext[ids[s]], ap[s]);

    // single pass over logits: cache in regs + sum of exp
    const float* lg = logits + (size_t)t * NVOC;
    float lgv[32];
    float ssum = 0.0f;
    #pragma unroll
    for (int j = 0; j < 32; j++) {
        int v = tid + j * 1024;
        if (v < NVOC) { lgv[j] = lg[v]; ssum += __expf(lgv[j]); }
        else lgv[j] = 0.0f;
    }
    ssum = warp_sum(ssum);
    if (lane == 0) red[wid] = ssum;
    __syncthreads();            // also fences the scatter atomics
    if (wid == 0) {
        float x = red[lane];
        x = warp_sum(x);
        if (lane == 0) red[0] = x;
    }
    __syncthreads();
    const float lse = __logf(red[0]);

    const float lk    = g_lk[t];
    const float copyp = __expf(g_lc[t]);

    float* op = out + (size_t)t * EXTV;
    #pragma unroll
    for (int j = 0; j < 36; j++) {
        int v = tid + j * 1024;
        if (v >= EXTV) break;
        float base = (v < NVOC) ? (lgv[j] - lse + lk) : -1e9f;
        float e = ext[v];
        float o;
        if (e > 0.0f) o = __logf(__expf(base) + e * copyp);
        else          o = base;
        op[v] = o;
    }
}

// ---------------- host launcher ---------------------------------------------
extern "C" void kernel_launch(void* const* d_in, const int* in_sizes, int n_in,
                              void* d_out, int out_size)
{
    const float* logits = (const float*)d_in[0];
    const int*   ids    = (const int*)d_in[1];
    const float* src    = (const float*)d_in[2];
    const float* tgt    = (const float*)d_in[3];
    const float* w_lin;
    const float* b_lin;
    const float* Wq;
    const float* Wk;
    if (n_in >= 9 && in_sizes[4] == 1) {
        w_lin = (const float*)d_in[5];
        b_lin = (const float*)d_in[6];
        Wq    = (const float*)d_in[7];
        Wk    = (const float*)d_in[8];
    } else {
        w_lin = (const float*)d_in[4];
        b_lin = (const float*)d_in[5];
        Wq    = (const float*)d_in[6];
        Wk    = (const float*)d_in[7];
    }

    static bool   inited = false;
    static float* pQ = nullptr;
    static float* pK = nullptr;
    if (!inited) {
        cudaFuncSetAttribute(final_kernel,
                             cudaFuncAttributeMaxDynamicSharedMemorySize,
                             (EXTV + 32) * (int)sizeof(float));
        void* tmp;
        cudaGetSymbolAddress(&tmp, g_Q); pQ = (float*)tmp;
        cudaGetSymbolAddress(&tmp, g_K); pK = (float*)tmp;
        inited = true;
    }

    float* out = (float*)d_out;

    // 1) gating scalars
    z_kernel<<<TGTN / 8, 256>>>(tgt, w_lin, b_lin);

    // 2) projections (tensor cores, tf32)
    proj_gemm_t<<<dim3(DIMN / 128, TGTN / 128), 256>>>(tgt, Wq, pQ);
    proj_gemm_t<<<dim3(DIMN / 128, SRCN / 128), 256>>>(src, Wk, pK);

    // 3) per-head raw scores (tensor cores, tf32 -> bf16)
    scores_gemm_t<<<dim3(SRCN / 128, TGTN / 128, NHEAD), 256>>>();

    // 4) softmax + head mean
    softmax_mean<<<TGTN, 256>>>();

    // 5) fused scatter + log_softmax + combine
    final_kernel<<<TGTN, 1024, (EXTV + 32) * (int)sizeof(float)>>>(logits, ids, out);
}